// round 2
// baseline (speedup 1.0000x reference)
#include <cuda_runtime.h>

#define DD 128           // feature dim
#define NPOW 17          // A^0 .. A^16
#define TMAX 64

// Scratch: __device__ globals (no allocation allowed)
__device__ __align__(256) float g_Wp[NPOW][DD * DD];   // A^k, A = dt*W
__device__ __align__(256) float g_P[TMAX][DD * DD];    // P_t = expm(t*dt*W)

// ---------------------------------------------------------------------------
// 1) g_Wp[0] = I, g_Wp[1] = dt * W
// ---------------------------------------------------------------------------
__global__ void init_kernel(const float* __restrict__ W) {
    int i = blockIdx.x * blockDim.x + threadIdx.x;   // 0..16383
    int r = i >> 7, c = i & 127;
    g_Wp[0][i] = (r == c) ? 1.0f : 0.0f;
    g_Wp[1][i] = 0.01f * W[i];
}

// ---------------------------------------------------------------------------
// 2) Doubling round: for i = 1..m (blockIdx.z): Wp[m+i] = Wp[m] @ Wp[i]
//    64x64 tile per block, 256 threads, 4x4 micro-tile, BK=32
// ---------------------------------------------------------------------------
__global__ void power_round_kernel(int m) {
    int i = blockIdx.z + 1;
    const float* __restrict__ A = g_Wp[m];
    const float* __restrict__ B = g_Wp[i];
    float* __restrict__ C = g_Wp[m + i];

    __shared__ float As[32][64];
    __shared__ float Bs[32][64];

    int tid = threadIdx.x;
    int tx = tid & 15, ty = tid >> 4;
    int row0 = blockIdx.x * 64, col0 = blockIdx.y * 64;

    float acc[4][4];
#pragma unroll
    for (int a = 0; a < 4; a++)
#pragma unroll
        for (int b = 0; b < 4; b++) acc[a][b] = 0.0f;

    for (int kb = 0; kb < DD; kb += 32) {
#pragma unroll
        for (int l = 0; l < 2; l++) {
            int idx = tid + l * 256;
            int r = idx >> 3;           // 0..63
            int c4 = (idx & 7) * 4;     // 0..28
            float4 v = *(const float4*)(A + (size_t)(row0 + r) * DD + kb + c4);
            As[c4 + 0][r] = v.x; As[c4 + 1][r] = v.y;
            As[c4 + 2][r] = v.z; As[c4 + 3][r] = v.w;
        }
#pragma unroll
        for (int l = 0; l < 2; l++) {
            int idx = tid + l * 256;
            int k = idx >> 4;           // 0..31
            int c4 = (idx & 15) * 4;    // 0..60
            *(float4*)&Bs[k][c4] =
                *(const float4*)(B + (size_t)(kb + k) * DD + col0 + c4);
        }
        __syncthreads();
#pragma unroll
        for (int k = 0; k < 32; k++) {
            float4 a4 = *(float4*)&As[k][ty * 4];
            float4 b4 = *(float4*)&Bs[k][tx * 4];
            float av[4] = {a4.x, a4.y, a4.z, a4.w};
            float bv[4] = {b4.x, b4.y, b4.z, b4.w};
#pragma unroll
            for (int a = 0; a < 4; a++)
#pragma unroll
                for (int b = 0; b < 4; b++) acc[a][b] += av[a] * bv[b];
        }
        __syncthreads();
    }
#pragma unroll
    for (int a = 0; a < 4; a++) {
        float4 v = make_float4(acc[a][0], acc[a][1], acc[a][2], acc[a][3]);
        *(float4*)(C + (size_t)(row0 + ty * 4 + a) * DD + col0 + tx * 4) = v;
    }
}

// ---------------------------------------------------------------------------
// 3) P_t = sum_k (t^k / k!) * A^k   (elementwise over the 17 power matrices)
// ---------------------------------------------------------------------------
__global__ void combine_kernel() {
    int i = blockIdx.x * blockDim.x + threadIdx.x;  // 0..16383
    int t = blockIdx.y;
    float tf = (float)t;
    float c = 1.0f, s = 0.0f;
#pragma unroll
    for (int k = 0; k < NPOW; k++) {
        s += c * g_Wp[k][i];
        c *= tf / (float)(k + 1);
    }
    g_P[t][i] = s;
}

// ---------------------------------------------------------------------------
// 4) out[b, t, :] = x[b, :] @ P_t
//    Block: 128 rows of x * one t.  256 threads, 8x8 micro-tile, BK=16.
// ---------------------------------------------------------------------------
__global__ void __launch_bounds__(256, 2)
gemm_kernel(const float* __restrict__ x, float* __restrict__ out, int T) {
    __shared__ float As[16][DD];
    __shared__ float Bs[16][DD];

    int tid = threadIdx.x;
    int tx = tid & 15, ty = tid >> 4;
    int t = blockIdx.y;
    const float* __restrict__ P = g_P[t];
    size_t R0 = (size_t)blockIdx.x * 128;

    float acc[8][8];
#pragma unroll
    for (int a = 0; a < 8; a++)
#pragma unroll
        for (int b = 0; b < 8; b++) acc[a][b] = 0.0f;

    for (int kb = 0; kb < DD; kb += 16) {
#pragma unroll
        for (int l = 0; l < 2; l++) {
            int idx = tid + l * 256;
            int r = idx >> 2;           // 0..127
            int c4 = (idx & 3) * 4;     // 0,4,8,12
            float4 v = *(const float4*)(x + (R0 + r) * DD + kb + c4);
            As[c4 + 0][r] = v.x; As[c4 + 1][r] = v.y;
            As[c4 + 2][r] = v.z; As[c4 + 3][r] = v.w;
        }
#pragma unroll
        for (int l = 0; l < 2; l++) {
            int idx = tid + l * 256;
            int k = idx >> 5;           // 0..15
            int c4 = (idx & 31) * 4;    // 0..124
            *(float4*)&Bs[k][c4] =
                *(const float4*)(P + (size_t)(kb + k) * DD + c4);
        }
        __syncthreads();
#pragma unroll
        for (int k = 0; k < 16; k++) {
            float a[8], b[8];
            *(float4*)&a[0] = *(float4*)&As[k][ty * 8];
            *(float4*)&a[4] = *(float4*)&As[k][ty * 8 + 4];
            *(float4*)&b[0] = *(float4*)&Bs[k][tx * 8];
            *(float4*)&b[4] = *(float4*)&Bs[k][tx * 8 + 4];
#pragma unroll
            for (int p = 0; p < 8; p++)
#pragma unroll
                for (int q = 0; q < 8; q++) acc[p][q] += a[p] * b[q];
        }
        __syncthreads();
    }

#pragma unroll
    for (int p = 0; p < 8; p++) {
        size_t row = R0 + ty * 8 + p;
        float* o = out + (row * (size_t)T + t) * DD + tx * 8;
        *(float4*)(o + 0) = make_float4(acc[p][0], acc[p][1], acc[p][2], acc[p][3]);
        *(float4*)(o + 4) = make_float4(acc[p][4], acc[p][5], acc[p][6], acc[p][7]);
    }
}

// ---------------------------------------------------------------------------
extern "C" void kernel_launch(void* const* d_in, const int* in_sizes, int n_in,
                              void* d_out, int out_size) {
    const float* x = (const float*)d_in[0];   // (B, 128)
    const float* W = (const float*)d_in[1];   // (128, 128)
    float* out = (float*)d_out;               // (B, T, 128)

    int B = in_sizes[0] / DD;                 // 8192
    int T = out_size / in_sizes[0];           // 64
    if (T > TMAX) T = TMAX;

    // Propagators
    init_kernel<<<(DD * DD) / 256, 256>>>(W);
    for (int m = 1; m <= 8; m <<= 1)
        power_round_kernel<<<dim3(2, 2, m), 256>>>(m);
    combine_kernel<<<dim3((DD * DD) / 256, T), 256>>>();

    // Main GEMM: out[:, t, :] = x @ P_t
    gemm_kernel<<<dim3(B / 128, T), 256>>>(x, out, T);
}

// round 4
// speedup vs baseline: 3.3317x; 3.3317x over previous
#include <cuda_runtime.h>
#include <cuda_bf16.h>
#include <cstdint>

#define DD 128
#define TT 64
#define NPOW 17
#define BB 8192

// ---------------- device scratch (no allocs allowed) ----------------
__device__ __align__(1024) float g_Wp[NPOW][DD * DD];        // A^k, A = dt*W
__device__ __align__(1024) __nv_bfloat16 g_Bhi[TT][DD * DD]; // P_t hi, row-major [k][n]
__device__ __align__(1024) __nv_bfloat16 g_Blo[TT][DD * DD]; // P_t lo
__device__ __align__(1024) __nv_bfloat16 g_xhi[BB * DD];
__device__ __align__(1024) __nv_bfloat16 g_xlo[BB * DD];

// ---------------- helpers ----------------
__device__ __forceinline__ uint32_t smem_u32(const void* p) {
    uint32_t a;
    asm("{ .reg .u64 t; cvta.to.shared.u64 t, %1; cvt.u32.u64 %0, t; }" : "=r"(a) : "l"(p));
    return a;
}
__device__ __forceinline__ void ldsm4(uint32_t* r, uint32_t a) {
    asm volatile("ldmatrix.sync.aligned.m8n8.x4.shared.b16 {%0,%1,%2,%3}, [%4];"
                 : "=r"(r[0]), "=r"(r[1]), "=r"(r[2]), "=r"(r[3]) : "r"(a));
}
__device__ __forceinline__ void ldsm4t(uint32_t* r, uint32_t a) {
    asm volatile("ldmatrix.sync.aligned.m8n8.x4.trans.shared.b16 {%0,%1,%2,%3}, [%4];"
                 : "=r"(r[0]), "=r"(r[1]), "=r"(r[2]), "=r"(r[3]) : "r"(a));
}
__device__ __forceinline__ void mma16816(float* d, const uint32_t* a,
                                         uint32_t b0, uint32_t b1) {
    asm volatile(
        "mma.sync.aligned.m16n8k16.row.col.f32.bf16.bf16.f32 "
        "{%0,%1,%2,%3}, {%4,%5,%6,%7}, {%8,%9}, {%0,%1,%2,%3};"
        : "+f"(d[0]), "+f"(d[1]), "+f"(d[2]), "+f"(d[3])
        : "r"(a[0]), "r"(a[1]), "r"(a[2]), "r"(a[3]), "r"(b0), "r"(b1));
}

// ---------------- prologue kernels ----------------
__global__ void xsplit_kernel(const float* __restrict__ x) {
    int i = blockIdx.x * 256 + threadIdx.x;
    float v = x[i];
    __nv_bfloat16 h = __float2bfloat16(v);
    g_xhi[i] = h;
    g_xlo[i] = __float2bfloat16(v - __bfloat162float(h));
}

__global__ void init_kernel(const float* __restrict__ W) {
    int i = blockIdx.x * 256 + threadIdx.x;
    int r = i >> 7, c = i & 127;
    g_Wp[0][i] = (r == c) ? 1.0f : 0.0f;
    g_Wp[1][i] = 0.01f * W[i];
}

// C = Wp[m] @ Wp[i], i = blockIdx.y+1.  32x32 tile, full K, latency-optimized.
__global__ void power_round_kernel(int m) {
    int i = blockIdx.y + 1;
    const float* __restrict__ A = g_Wp[m];
    const float* __restrict__ Bm = g_Wp[i];
    float* __restrict__ C = g_Wp[m + i];

    __shared__ float As[DD][33];  // [k][r]
    __shared__ float Bs[DD][33];  // [k][c]
    int tid = threadIdx.x;
    int r0 = (blockIdx.x >> 2) * 32, c0 = (blockIdx.x & 3) * 32;

#pragma unroll
    for (int j = 0; j < 4; j++) {
        int q = tid + j * 256;
        int r = q >> 5, k4 = (q & 31) * 4;
        float4 v = *(const float4*)(A + (r0 + r) * DD + k4);
        As[k4 + 0][r] = v.x; As[k4 + 1][r] = v.y;
        As[k4 + 2][r] = v.z; As[k4 + 3][r] = v.w;
    }
#pragma unroll
    for (int j = 0; j < 4; j++) {
        int q = tid + j * 256;
        int k = q >> 3, c4 = (q & 7) * 4;
        float4 v = *(const float4*)(Bm + k * DD + c0 + c4);
        Bs[k][c4 + 0] = v.x; Bs[k][c4 + 1] = v.y;
        Bs[k][c4 + 2] = v.z; Bs[k][c4 + 3] = v.w;
    }
    __syncthreads();

    int r = (tid >> 4) << 1, c = (tid & 15) << 1;
    float a00 = 0, a01 = 0, a10 = 0, a11 = 0;
#pragma unroll
    for (int k = 0; k < DD; k++) {
        float x0 = As[k][r], x1 = As[k][r + 1];
        float y0 = Bs[k][c], y1 = Bs[k][c + 1];
        a00 += x0 * y0; a01 += x0 * y1;
        a10 += x1 * y0; a11 += x1 * y1;
    }
    C[(r0 + r) * DD + c0 + c] = a00;     C[(r0 + r) * DD + c0 + c + 1] = a01;
    C[(r0 + r + 1) * DD + c0 + c] = a10; C[(r0 + r + 1) * DD + c0 + c + 1] = a11;
}

// P_t = sum_k (t^k/k!) A^k, then split fp32 -> bf16 hi/lo (row-major, no transpose)
__global__ void combine_split_kernel() {
    int i = blockIdx.x * 256 + threadIdx.x;  // k*128 + n
    int t = blockIdx.y;
    float tf = (float)t, c = 1.0f, s = 0.0f;
#pragma unroll
    for (int k = 0; k < NPOW; k++) {
        s += c * g_Wp[k][i];
        c *= tf / (float)(k + 1);
    }
    __nv_bfloat16 h = __float2bfloat16(s);
    g_Bhi[t][i] = h;
    g_Blo[t][i] = __float2bfloat16(s - __bfloat162float(h));
}

// ---------------- main GEMM: warp mma.sync, split-bf16 x3 ----------------
// CTA: M=128 (x rows), N=64 (half of D, blockIdx.z), K=128 all-resident.
// smem: A hi/lo [128][128] pad->stride 136 elem (272B); B hi/lo [128][64] stride 72 (144B)
#define A_STRIDE 272            // bytes
#define B_STRIDE 144
#define SM_AHI 0
#define SM_ALO (SM_AHI + 128 * A_STRIDE)      // 34816
#define SM_BHI (SM_ALO + 128 * A_STRIDE)      // 69632
#define SM_BLO (SM_BHI + 128 * B_STRIDE)      // 88064
#define SM_TOTAL (SM_BLO + 128 * B_STRIDE)    // 106496

__global__ void __launch_bounds__(256, 2)
gemm_kernel(float* __restrict__ out) {
    extern __shared__ __align__(16) char smem[];
    int tid = threadIdx.x;
    int rb = blockIdx.x, t = blockIdx.y, z = blockIdx.z;

    // ---- load tiles (padded, vectorized) ----
    const __nv_bfloat16* Ah = g_xhi + (size_t)rb * 128 * DD;
    const __nv_bfloat16* Al = g_xlo + (size_t)rb * 128 * DD;
    const __nv_bfloat16* Bh = g_Bhi[t] + z * 64;
    const __nv_bfloat16* Bl = g_Blo[t] + z * 64;

#pragma unroll
    for (int j = 0; j < 8; j++) {           // A: 128 rows x 16 chunks of 16B
        int idx = j * 256 + tid;
        int row = idx >> 4, c = idx & 15;
        int so = row * A_STRIDE + c * 16;
        int go = row * DD + c * 8;
        *(float4*)(smem + SM_AHI + so) = *(const float4*)(Ah + go);
        *(float4*)(smem + SM_ALO + so) = *(const float4*)(Al + go);
    }
#pragma unroll
    for (int j = 0; j < 4; j++) {           // B: 128 rows x 8 chunks of 16B
        int idx = j * 256 + tid;
        int row = idx >> 3, c = idx & 7;
        int so = row * B_STRIDE + c * 16;
        int go = row * DD + c * 8;
        *(float4*)(smem + SM_BHI + so) = *(const float4*)(Bh + go);
        *(float4*)(smem + SM_BLO + so) = *(const float4*)(Bl + go);
    }
    __syncthreads();

    // ---- warp MMA ----
    int wid = tid >> 5, lane = tid & 31;
    int wm = wid & 3, wn = wid >> 2;        // 4 x 2 warp grid; warp tile 32x64? no: 32(m) x 32(n)
    uint32_t sb = smem_u32(smem);

    // ldmatrix per-lane addresses
    uint32_t offA = (uint32_t)((wm * 32 + (lane & 15)) * A_STRIDE + (lane >> 4) * 16);
    uint32_t offB = (uint32_t)(((lane & 7) + ((lane >> 3) & 1) * 8) * B_STRIDE +
                               (wn * 32 + (lane >> 4) * 8) * 2);

    uint32_t A_p[3] = {sb + SM_AHI + offA, sb + SM_AHI + offA, sb + SM_ALO + offA};
    uint32_t B_p[3] = {sb + SM_BHI + offB, sb + SM_BLO + offB, sb + SM_BHI + offB};

    float acc[2][4][4];
#pragma unroll
    for (int i = 0; i < 2; i++)
#pragma unroll
        for (int j = 0; j < 4; j++)
#pragma unroll
            for (int k = 0; k < 4; k++) acc[i][j][k] = 0.0f;

#pragma unroll
    for (int p = 0; p < 3; p++) {
        uint32_t Ab = A_p[p], Bb = B_p[p];
#pragma unroll
        for (int ks = 0; ks < 8; ks++) {
            uint32_t a0[4], a1[4], b0[4], b1[4];
            ldsm4(a0, Ab + ks * 32);                       // rows wm*32+0..15
            ldsm4(a1, Ab + ks * 32 + 16 * A_STRIDE);       // rows +16..31
            ldsm4t(b0, Bb + ks * 16 * B_STRIDE);           // n-blocks 0,1
            ldsm4t(b1, Bb + ks * 16 * B_STRIDE + 32);      // n-blocks 2,3
            mma16816(acc[0][0], a0, b0[0], b0[1]);
            mma16816(acc[0][1], a0, b0[2], b0[3]);
            mma16816(acc[0][2], a0, b1[0], b1[1]);
            mma16816(acc[0][3], a0, b1[2], b1[3]);
            mma16816(acc[1][0], a1, b0[0], b0[1]);
            mma16816(acc[1][1], a1, b0[2], b0[3]);
            mma16816(acc[1][2], a1, b1[0], b1[1]);
            mma16816(acc[1][3], a1, b1[2], b1[3]);
        }
    }

    // ---- epilogue: direct coalesced STG.64 (4 lanes x 8B = full 32B sectors) ----
    int g = lane >> 2, q = lane & 3;
    size_t rowbase = (size_t)rb * 128 + wm * 32;
#pragma unroll
    for (int mt = 0; mt < 2; mt++) {
        size_t row = rowbase + mt * 16 + g;
#pragma unroll
        for (int nb = 0; nb < 4; nb++) {
            int col = z * 64 + wn * 32 + nb * 8 + q * 2;
            float* o = out + (row * TT + t) * DD + col;
            *(float2*)o = make_float2(acc[mt][nb][0], acc[mt][nb][1]);
            *(float2*)(o + (size_t)8 * TT * DD) = make_float2(acc[mt][nb][2], acc[mt][nb][3]);
        }
    }
}

// ---------------- launch ----------------
extern "C" void kernel_launch(void* const* d_in, const int* in_sizes, int n_in,
                              void* d_out, int out_size) {
    const float* x = (const float*)d_in[0];
    const float* W = (const float*)d_in[1];
    float* out = (float*)d_out;

    xsplit_kernel<<<(BB * DD) / 256, 256>>>(x);
    init_kernel<<<(DD * DD) / 256, 256>>>(W);
    for (int m = 1; m <= 8; m <<= 1)
        power_round_kernel<<<dim3(16, m), 256>>>(m);
    combine_split_kernel<<<dim3((DD * DD) / 256, TT), 256>>>();

    cudaFuncSetAttribute(gemm_kernel, cudaFuncAttributeMaxDynamicSharedMemorySize, SM_TOTAL);
    gemm_kernel<<<dim3(BB / 128, TT, 2), 256, SM_TOTAL>>>(out);
}

// round 7
// speedup vs baseline: 4.3078x; 1.2930x over previous
#include <cuda_runtime.h>
#include <cuda_fp16.h>
#include <cstdint>

#define DD 128
#define TT 64
#define NPOW 10          // A^0 .. A^9  (Taylor K=9; ||63*dt*W|| ~ 1.26, tail ~3e-6)
#define BB 8192

// ---------------- device scratch (no allocs allowed) ----------------
__device__ __align__(1024) float g_Wp[NPOW][DD * DD];   // A^k, A = dt*W
__device__ __align__(1024) __half g_Bf[TT][DD * DD];    // P_t fp16, row-major [k][n]
__device__ __align__(1024) __half g_xhi[BB * DD];
__device__ __align__(1024) __half g_xlo[BB * DD];

// ---------------- helpers ----------------
__device__ __forceinline__ uint32_t smem_u32(const void* p) {
    uint32_t a;
    asm("{ .reg .u64 t; cvta.to.shared.u64 t, %1; cvt.u32.u64 %0, t; }" : "=r"(a) : "l"(p));
    return a;
}
__device__ __forceinline__ void ldsm4(uint32_t* r, uint32_t a) {
    asm volatile("ldmatrix.sync.aligned.m8n8.x4.shared.b16 {%0,%1,%2,%3}, [%4];"
                 : "=r"(r[0]), "=r"(r[1]), "=r"(r[2]), "=r"(r[3]) : "r"(a));
}
__device__ __forceinline__ void ldsm4t(uint32_t* r, uint32_t a) {
    asm volatile("ldmatrix.sync.aligned.m8n8.x4.trans.shared.b16 {%0,%1,%2,%3}, [%4];"
                 : "=r"(r[0]), "=r"(r[1]), "=r"(r[2]), "=r"(r[3]) : "r"(a));
}
__device__ __forceinline__ void mma16816(float* d, const uint32_t* a,
                                         uint32_t b0, uint32_t b1) {
    asm volatile(
        "mma.sync.aligned.m16n8k16.row.col.f32.f16.f16.f32 "
        "{%0,%1,%2,%3}, {%4,%5,%6,%7}, {%8,%9}, {%0,%1,%2,%3};"
        : "+f"(d[0]), "+f"(d[1]), "+f"(d[2]), "+f"(d[3])
        : "r"(a[0]), "r"(a[1]), "r"(a[2]), "r"(a[3]), "r"(b0), "r"(b1));
}

// ---------------- prologue kernels ----------------
__global__ void xsplit_kernel(const float* __restrict__ x) {
    int i = blockIdx.x * 256 + threadIdx.x;
    float v = x[i];
    __half h = __float2half(v);
    g_xhi[i] = h;
    g_xlo[i] = __float2half(v - __half2float(h));
}

__global__ void init_kernel(const float* __restrict__ W) {
    int i = blockIdx.x * 256 + threadIdx.x;
    int r = i >> 7, c = i & 127;
    g_Wp[0][i] = (r == c) ? 1.0f : 0.0f;
    g_Wp[1][i] = 0.01f * W[i];
}

// C = Wp[m] @ Wp[i], i = blockIdx.y+1.  32x32 tile, full K.
__global__ void power_round_kernel(int m) {
    int i = blockIdx.y + 1;
    const float* __restrict__ A = g_Wp[m];
    const float* __restrict__ Bm = g_Wp[i];
    float* __restrict__ C = g_Wp[m + i];

    __shared__ float As[DD][33];  // [k][r]
    __shared__ float Bs[DD][33];  // [k][c]
    int tid = threadIdx.x;
    int r0 = (blockIdx.x >> 2) * 32, c0 = (blockIdx.x & 3) * 32;

#pragma unroll
    for (int j = 0; j < 4; j++) {
        int q = tid + j * 256;
        int r = q >> 5, k4 = (q & 31) * 4;
        float4 v = *(const float4*)(A + (r0 + r) * DD + k4);
        As[k4 + 0][r] = v.x; As[k4 + 1][r] = v.y;
        As[k4 + 2][r] = v.z; As[k4 + 3][r] = v.w;
    }
#pragma unroll
    for (int j = 0; j < 4; j++) {
        int q = tid + j * 256;
        int k = q >> 3, c4 = (q & 7) * 4;
        float4 v = *(const float4*)(Bm + k * DD + c0 + c4);
        Bs[k][c4 + 0] = v.x; Bs[k][c4 + 1] = v.y;
        Bs[k][c4 + 2] = v.z; Bs[k][c4 + 3] = v.w;
    }
    __syncthreads();

    int r = (tid >> 4) << 1, c = (tid & 15) << 1;
    float a00 = 0, a01 = 0, a10 = 0, a11 = 0;
#pragma unroll
    for (int k = 0; k < DD; k++) {
        float x0 = As[k][r], x1 = As[k][r + 1];
        float y0 = Bs[k][c], y1 = Bs[k][c + 1];
        a00 += x0 * y0; a01 += x0 * y1;
        a10 += x1 * y0; a11 += x1 * y1;
    }
    C[(r0 + r) * DD + c0 + c] = a00;     C[(r0 + r) * DD + c0 + c + 1] = a01;
    C[(r0 + r + 1) * DD + c0 + c] = a10; C[(r0 + r + 1) * DD + c0 + c + 1] = a11;
}

// P_t = sum_{k<NPOW} (t^k/k!) A^k  -> fp16
__global__ void combine_kernel() {
    int i = blockIdx.x * 256 + threadIdx.x;  // k*128 + n
    int t = blockIdx.y;
    float tf = (float)t, c = 1.0f, s = 0.0f;
#pragma unroll
    for (int k = 0; k < NPOW; k++) {
        s += c * g_Wp[k][i];
        c *= tf / (float)(k + 1);
    }
    g_Bf[t][i] = __float2half(s);
}

// ---------------- main GEMM: warp mma.sync, fp16 x2 products ----------------
// CTA: M=128, N=128, K=128 all-resident; 8 warps as 4(m) x 2(n), warp tile 32x64.
#define A_STRIDE 272            // bytes: 128 fp16 + 8 pad
#define SM_AHI 0
#define SM_ALO (SM_AHI + 128 * A_STRIDE)      // 34816
#define SM_B   (SM_ALO + 128 * A_STRIDE)      // 69632
#define SM_TOTAL (SM_B + 128 * A_STRIDE)      // 104448

__global__ void __launch_bounds__(256, 2)
gemm_kernel(float* __restrict__ out) {
    extern __shared__ __align__(16) char smem[];
    int tid = threadIdx.x;
    int rb = blockIdx.x, t = blockIdx.y;

    // ---- load tiles (padded, vectorized) ----
    const __half* Ah = g_xhi + (size_t)rb * 128 * DD;
    const __half* Al = g_xlo + (size_t)rb * 128 * DD;
    const __half* Bf = g_Bf[t];

#pragma unroll
    for (int j = 0; j < 8; j++) {           // 128 rows x 16 chunks of 16B
        int idx = j * 256 + tid;
        int row = idx >> 4, c = idx & 15;
        int so = row * A_STRIDE + c * 16;
        int go = row * DD + c * 8;
        *(float4*)(smem + SM_AHI + so) = *(const float4*)(Ah + go);
        *(float4*)(smem + SM_ALO + so) = *(const float4*)(Al + go);
        *(float4*)(smem + SM_B + so)   = *(const float4*)(Bf + go);
    }
    __syncthreads();

    // ---- warp MMA ----
    int wid = tid >> 5, lane = tid & 31;
    int wm = wid & 3, wn = wid >> 2;        // warp tile: rows wm*32+0..31, cols wn*64+0..63
    uint32_t sb = smem_u32(smem);

    uint32_t offA = (uint32_t)((wm * 32 + (lane & 15)) * A_STRIDE + (lane >> 4) * 16);
    uint32_t offB = (uint32_t)(((lane & 7) + ((lane >> 3) & 1) * 8) * A_STRIDE +
                               (wn * 64 + (lane >> 4) * 8) * 2);

    uint32_t A_p[2] = {sb + SM_AHI + offA, sb + SM_ALO + offA};
    uint32_t Bb = sb + SM_B + offB;

    float acc[2][8][4];
#pragma unroll
    for (int i = 0; i < 2; i++)
#pragma unroll
        for (int j = 0; j < 8; j++)
#pragma unroll
            for (int k = 0; k < 4; k++) acc[i][j][k] = 0.0f;

#pragma unroll
    for (int p = 0; p < 2; p++) {
        uint32_t Ab = A_p[p];
#pragma unroll
        for (int ks = 0; ks < 8; ks++) {
            uint32_t a0[4], a1[4];
            ldsm4(a0, Ab + ks * 32);                     // rows wm*32+0..15
            ldsm4(a1, Ab + ks * 32 + 16 * A_STRIDE);     // rows +16..31
#pragma unroll
            for (int j = 0; j < 4; j++) {                // each ldsm4t = 16 n-cols
                uint32_t b[4];
                ldsm4t(b, Bb + ks * 16 * A_STRIDE + j * 32);   // FIX: +32B = 16 cols per step
                mma16816(acc[0][2 * j],     a0, b[0], b[1]);
                mma16816(acc[0][2 * j + 1], a0, b[2], b[3]);
                mma16816(acc[1][2 * j],     a1, b[0], b[1]);
                mma16816(acc[1][2 * j + 1], a1, b[2], b[3]);
            }
        }
    }

    // ---- epilogue: direct coalesced STG.64 ----
    int g = lane >> 2, q = lane & 3;
    size_t rowbase = (size_t)rb * 128 + wm * 32;
#pragma unroll
    for (int mt = 0; mt < 2; mt++) {
        size_t row = rowbase + mt * 16 + g;
#pragma unroll
        for (int nb = 0; nb < 8; nb++) {
            int col = wn * 64 + nb * 8 + q * 2;
            float* o = out + (row * TT + t) * DD + col;
            *(float2*)o = make_float2(acc[mt][nb][0], acc[mt][nb][1]);
            *(float2*)(o + (size_t)8 * TT * DD) = make_float2(acc[mt][nb][2], acc[mt][nb][3]);
        }
    }
}

// ---------------- launch ----------------
extern "C" void kernel_launch(void* const* d_in, const int* in_sizes, int n_in,
                              void* d_out, int out_size) {
    const float* x = (const float*)d_in[0];
    const float* W = (const float*)d_in[1];
    float* out = (float*)d_out;

    xsplit_kernel<<<(BB * DD) / 256, 256>>>(x);
    init_kernel<<<(DD * DD) / 256, 256>>>(W);
    power_round_kernel<<<dim3(16, 1), 256>>>(1);   // A^2
    power_round_kernel<<<dim3(16, 2), 256>>>(2);   // A^3, A^4
    power_round_kernel<<<dim3(16, 4), 256>>>(4);   // A^5..A^8
    power_round_kernel<<<dim3(16, 1), 256>>>(8);   // A^9
    combine_kernel<<<dim3((DD * DD) / 256, TT), 256>>>();

    cudaFuncSetAttribute(gemm_kernel, cudaFuncAttributeMaxDynamicSharedMemorySize, SM_TOTAL);
    gemm_kernel<<<dim3(BB / 128, TT), 256, SM_TOTAL>>>(out);
}

// round 8
// speedup vs baseline: 6.4161x; 1.4894x over previous
#include <cuda_runtime.h>
#include <cuda_fp16.h>
#include <cstdint>

#define DD 128
#define TT 64
#define NPOW 9           // A^0 .. A^8 (Taylor K=8; tail ~1e-5 relative)
#define BB 8192

// ---------------- device scratch (no allocs allowed) ----------------
__device__ __align__(1024) float g_Wp[NPOW][DD * DD];   // A^k, A = dt*W
__device__ __align__(1024) __half g_Bf[TT][DD * DD];    // P_t fp16, row-major [k][n]
__device__ __align__(1024) __half g_xh[BB * DD];        // x fp16

// ---------------- helpers ----------------
__device__ __forceinline__ uint32_t smem_u32(const void* p) {
    uint32_t a;
    asm("{ .reg .u64 t; cvta.to.shared.u64 t, %1; cvt.u32.u64 %0, t; }" : "=r"(a) : "l"(p));
    return a;
}
__device__ __forceinline__ void ldsm4(uint32_t* r, uint32_t a) {
    asm volatile("ldmatrix.sync.aligned.m8n8.x4.shared.b16 {%0,%1,%2,%3}, [%4];"
                 : "=r"(r[0]), "=r"(r[1]), "=r"(r[2]), "=r"(r[3]) : "r"(a));
}
__device__ __forceinline__ void ldsm4t(uint32_t* r, uint32_t a) {
    asm volatile("ldmatrix.sync.aligned.m8n8.x4.trans.shared.b16 {%0,%1,%2,%3}, [%4];"
                 : "=r"(r[0]), "=r"(r[1]), "=r"(r[2]), "=r"(r[3]) : "r"(a));
}
__device__ __forceinline__ void mma16816(float* d, const uint32_t* a,
                                         uint32_t b0, uint32_t b1) {
    asm volatile(
        "mma.sync.aligned.m16n8k16.row.col.f32.f16.f16.f32 "
        "{%0,%1,%2,%3}, {%4,%5,%6,%7}, {%8,%9}, {%0,%1,%2,%3};"
        : "+f"(d[0]), "+f"(d[1]), "+f"(d[2]), "+f"(d[3])
        : "r"(a[0]), "r"(a[1]), "r"(a[2]), "r"(a[3]), "r"(b0), "r"(b1));
}

// ---------------- prologue kernels ----------------
// fused: x -> fp16, plus (first 64 blocks) init Wp[0]=I, Wp[1]=dt*W
__global__ void prep_kernel(const float* __restrict__ x, const float* __restrict__ W) {
    int i = blockIdx.x * 256 + threadIdx.x;
    g_xh[i] = __float2half(x[i]);
    if (i < DD * DD) {
        int r = i >> 7, c = i & 127;
        g_Wp[0][i] = (r == c) ? 1.0f : 0.0f;
        g_Wp[1][i] = 0.01f * W[i];
    }
}

// C = Wp[m] @ Wp[i], i = blockIdx.y+1.  32x32 tile, full K.
__global__ void power_round_kernel(int m) {
    int i = blockIdx.y + 1;
    const float* __restrict__ A = g_Wp[m];
    const float* __restrict__ Bm = g_Wp[i];
    float* __restrict__ C = g_Wp[m + i];

    __shared__ float As[DD][33];  // [k][r]
    __shared__ float Bs[DD][33];  // [k][c]
    int tid = threadIdx.x;
    int r0 = (blockIdx.x >> 2) * 32, c0 = (blockIdx.x & 3) * 32;

#pragma unroll
    for (int j = 0; j < 4; j++) {
        int q = tid + j * 256;
        int r = q >> 5, k4 = (q & 31) * 4;
        float4 v = *(const float4*)(A + (r0 + r) * DD + k4);
        As[k4 + 0][r] = v.x; As[k4 + 1][r] = v.y;
        As[k4 + 2][r] = v.z; As[k4 + 3][r] = v.w;
    }
#pragma unroll
    for (int j = 0; j < 4; j++) {
        int q = tid + j * 256;
        int k = q >> 3, c4 = (q & 7) * 4;
        float4 v = *(const float4*)(Bm + k * DD + c0 + c4);
        Bs[k][c4 + 0] = v.x; Bs[k][c4 + 1] = v.y;
        Bs[k][c4 + 2] = v.z; Bs[k][c4 + 3] = v.w;
    }
    __syncthreads();

    int r = (tid >> 4) << 1, c = (tid & 15) << 1;
    float a00 = 0, a01 = 0, a10 = 0, a11 = 0;
#pragma unroll
    for (int k = 0; k < DD; k++) {
        float x0 = As[k][r], x1 = As[k][r + 1];
        float y0 = Bs[k][c], y1 = Bs[k][c + 1];
        a00 += x0 * y0; a01 += x0 * y1;
        a10 += x1 * y0; a11 += x1 * y1;
    }
    C[(r0 + r) * DD + c0 + c] = a00;     C[(r0 + r) * DD + c0 + c + 1] = a01;
    C[(r0 + r + 1) * DD + c0 + c] = a10; C[(r0 + r + 1) * DD + c0 + c + 1] = a11;
}

// P_t = sum_{k<NPOW} (t^k/k!) A^k  -> fp16
__global__ void combine_kernel() {
    int i = blockIdx.x * 256 + threadIdx.x;  // k*128 + n
    int t = blockIdx.y;
    float tf = (float)t, c = 1.0f, s = 0.0f;
#pragma unroll
    for (int k = 0; k < NPOW; k++) {
        s += c * g_Wp[k][i];
        c *= tf / (float)(k + 1);
    }
    g_Bf[t][i] = __float2half(s);
}

// ---------------- main GEMM: warp mma.sync, single fp16 product ----------------
// CTA: M=128, N=128, K=128 all-resident; 8 warps as 4(m) x 2(n), warp tile 32x64.
#define A_STRIDE 272            // bytes: 128 fp16 + 8 pad
#define SM_A 0
#define SM_B (SM_A + 128 * A_STRIDE)          // 34816
#define SM_TOTAL (SM_B + 128 * A_STRIDE)      // 69632

__global__ void __launch_bounds__(256, 2)
gemm_kernel(float* __restrict__ out) {
    extern __shared__ __align__(16) char smem[];
    int tid = threadIdx.x;
    int rb = blockIdx.x, t = blockIdx.y;

    // ---- load tiles (padded, vectorized) ----
    const __half* Ah = g_xh + (size_t)rb * 128 * DD;
    const __half* Bf = g_Bf[t];

#pragma unroll
    for (int j = 0; j < 8; j++) {           // 128 rows x 16 chunks of 16B
        int idx = j * 256 + tid;
        int row = idx >> 4, c = idx & 15;
        int so = row * A_STRIDE + c * 16;
        int go = row * DD + c * 8;
        *(float4*)(smem + SM_A + so) = *(const float4*)(Ah + go);
        *(float4*)(smem + SM_B + so) = *(const float4*)(Bf + go);
    }
    __syncthreads();

    // ---- warp MMA ----
    int wid = tid >> 5, lane = tid & 31;
    int wm = wid & 3, wn = wid >> 2;        // warp tile: rows wm*32+0..31, cols wn*64+0..63
    uint32_t sb = smem_u32(smem);

    uint32_t Ab = sb + SM_A +
        (uint32_t)((wm * 32 + (lane & 15)) * A_STRIDE + (lane >> 4) * 16);
    uint32_t Bb = sb + SM_B +
        (uint32_t)(((lane & 7) + ((lane >> 3) & 1) * 8) * A_STRIDE +
                   (wn * 64 + (lane >> 4) * 8) * 2);

    float acc[2][8][4];
#pragma unroll
    for (int i = 0; i < 2; i++)
#pragma unroll
        for (int j = 0; j < 8; j++)
#pragma unroll
            for (int k = 0; k < 4; k++) acc[i][j][k] = 0.0f;

#pragma unroll
    for (int ks = 0; ks < 8; ks++) {
        uint32_t a0[4], a1[4];
        ldsm4(a0, Ab + ks * 32);                     // rows wm*32+0..15
        ldsm4(a1, Ab + ks * 32 + 16 * A_STRIDE);     // rows +16..31
#pragma unroll
        for (int j = 0; j < 4; j++) {                // each ldsm4t = 16 n-cols
            uint32_t b[4];
            ldsm4t(b, Bb + ks * 16 * A_STRIDE + j * 32);
            mma16816(acc[0][2 * j],     a0, b[0], b[1]);
            mma16816(acc[0][2 * j + 1], a0, b[2], b[3]);
            mma16816(acc[1][2 * j],     a1, b[0], b[1]);
            mma16816(acc[1][2 * j + 1], a1, b[2], b[3]);
        }
    }

    // ---- epilogue: direct coalesced STG.64 ----
    int g = lane >> 2, q = lane & 3;
    size_t rowbase = (size_t)rb * 128 + wm * 32;
#pragma unroll
    for (int mt = 0; mt < 2; mt++) {
        size_t row = rowbase + mt * 16 + g;
#pragma unroll
        for (int nb = 0; nb < 8; nb++) {
            int col = wn * 64 + nb * 8 + q * 2;
            float* o = out + (row * TT + t) * DD + col;
            *(float2*)o = make_float2(acc[mt][nb][0], acc[mt][nb][1]);
            *(float2*)(o + (size_t)8 * TT * DD) = make_float2(acc[mt][nb][2], acc[mt][nb][3]);
        }
    }
}

// ---------------- launch ----------------
extern "C" void kernel_launch(void* const* d_in, const int* in_sizes, int n_in,
                              void* d_out, int out_size) {
    const float* x = (const float*)d_in[0];
    const float* W = (const float*)d_in[1];
    float* out = (float*)d_out;

    prep_kernel<<<(BB * DD) / 256, 256>>>(x, W);
    power_round_kernel<<<dim3(16, 1), 256>>>(1);   // A^2
    power_round_kernel<<<dim3(16, 2), 256>>>(2);   // A^3, A^4
    power_round_kernel<<<dim3(16, 4), 256>>>(4);   // A^5..A^8
    combine_kernel<<<dim3((DD * DD) / 256, TT), 256>>>();

    cudaFuncSetAttribute(gemm_kernel, cudaFuncAttributeMaxDynamicSharedMemorySize, SM_TOTAL);
    gemm_kernel<<<dim3(BB / 128, TT), 256, SM_TOTAL>>>(out);
}

// round 9
// speedup vs baseline: 7.0401x; 1.0973x over previous
#include <cuda_runtime.h>
#include <cuda_fp16.h>
#include <cstdint>

#define DD 128
#define TT 64
#define NPOW 9           // A^0 .. A^8 (Taylor K=8; tail ~1e-5 relative)
#define BB 8192

// ---------------- device scratch (no allocs allowed) ----------------
__device__ __align__(1024) float g_Wp[NPOW][DD * DD];   // A^k, A = dt*W
__device__ __align__(1024) __half g_Bf[TT][DD * DD];    // P_t fp16, row-major [k][n]
__device__ __align__(1024) __half g_xh[BB * DD];        // x fp16

// ---------------- helpers ----------------
__device__ __forceinline__ uint32_t smem_u32(const void* p) {
    uint32_t a;
    asm("{ .reg .u64 t; cvta.to.shared.u64 t, %1; cvt.u32.u64 %0, t; }" : "=r"(a) : "l"(p));
    return a;
}
__device__ __forceinline__ void ldsm4(uint32_t* r, uint32_t a) {
    asm volatile("ldmatrix.sync.aligned.m8n8.x4.shared.b16 {%0,%1,%2,%3}, [%4];"
                 : "=r"(r[0]), "=r"(r[1]), "=r"(r[2]), "=r"(r[3]) : "r"(a));
}
__device__ __forceinline__ void ldsm4t(uint32_t* r, uint32_t a) {
    asm volatile("ldmatrix.sync.aligned.m8n8.x4.trans.shared.b16 {%0,%1,%2,%3}, [%4];"
                 : "=r"(r[0]), "=r"(r[1]), "=r"(r[2]), "=r"(r[3]) : "r"(a));
}
__device__ __forceinline__ void mma16816(float* d, const uint32_t* a,
                                         uint32_t b0, uint32_t b1) {
    asm volatile(
        "mma.sync.aligned.m16n8k16.row.col.f32.f16.f16.f32 "
        "{%0,%1,%2,%3}, {%4,%5,%6,%7}, {%8,%9}, {%0,%1,%2,%3};"
        : "+f"(d[0]), "+f"(d[1]), "+f"(d[2]), "+f"(d[3])
        : "r"(a[0]), "r"(a[1]), "r"(a[2]), "r"(a[3]), "r"(b0), "r"(b1));
}
__device__ __forceinline__ void cp16(uint32_t dst, const void* src) {
    asm volatile("cp.async.cg.shared.global [%0], [%1], 16;" :: "r"(dst), "l"(src));
}

// ---------------- prologue kernels ----------------
// fused: x -> fp16, plus (first 64 blocks) init Wp[0]=I, Wp[1]=dt*W
__global__ void prep_kernel(const float* __restrict__ x, const float* __restrict__ W) {
    int i = blockIdx.x * 256 + threadIdx.x;
    g_xh[i] = __float2half(x[i]);
    if (i < DD * DD) {
        int r = i >> 7, c = i & 127;
        g_Wp[0][i] = (r == c) ? 1.0f : 0.0f;
        g_Wp[1][i] = 0.01f * W[i];
    }
}

// C = Wp[m] @ Wp[i], i = blockIdx.y+1.  32x32 tile, full K.
__global__ void power_round_kernel(int m) {
    int i = blockIdx.y + 1;
    const float* __restrict__ A = g_Wp[m];
    const float* __restrict__ Bm = g_Wp[i];
    float* __restrict__ C = g_Wp[m + i];

    __shared__ float As[DD][33];  // [k][r]
    __shared__ float Bs[DD][33];  // [k][c]
    int tid = threadIdx.x;
    int r0 = (blockIdx.x >> 2) * 32, c0 = (blockIdx.x & 3) * 32;

#pragma unroll
    for (int j = 0; j < 4; j++) {
        int q = tid + j * 256;
        int r = q >> 5, k4 = (q & 31) * 4;
        float4 v = *(const float4*)(A + (r0 + r) * DD + k4);
        As[k4 + 0][r] = v.x; As[k4 + 1][r] = v.y;
        As[k4 + 2][r] = v.z; As[k4 + 3][r] = v.w;
    }
#pragma unroll
    for (int j = 0; j < 4; j++) {
        int q = tid + j * 256;
        int k = q >> 3, c4 = (q & 7) * 4;
        float4 v = *(const float4*)(Bm + k * DD + c0 + c4);
        Bs[k][c4 + 0] = v.x; Bs[k][c4 + 1] = v.y;
        Bs[k][c4 + 2] = v.z; Bs[k][c4 + 3] = v.w;
    }
    __syncthreads();

    int r = (tid >> 4) << 1, c = (tid & 15) << 1;
    float a00 = 0, a01 = 0, a10 = 0, a11 = 0;
#pragma unroll
    for (int k = 0; k < DD; k++) {
        float x0 = As[k][r], x1 = As[k][r + 1];
        float y0 = Bs[k][c], y1 = Bs[k][c + 1];
        a00 += x0 * y0; a01 += x0 * y1;
        a10 += x1 * y0; a11 += x1 * y1;
    }
    C[(r0 + r) * DD + c0 + c] = a00;     C[(r0 + r) * DD + c0 + c + 1] = a01;
    C[(r0 + r + 1) * DD + c0 + c] = a10; C[(r0 + r + 1) * DD + c0 + c + 1] = a11;
}

// P_t = sum_{k<NPOW} (t^k/k!) A^k  -> fp16
__global__ void combine_kernel() {
    int i = blockIdx.x * 256 + threadIdx.x;  // k*128 + n
    int t = blockIdx.y;
    float tf = (float)t, c = 1.0f, s = 0.0f;
#pragma unroll
    for (int k = 0; k < NPOW; k++) {
        s += c * g_Wp[k][i];
        c *= tf / (float)(k + 1);
    }
    g_Bf[t][i] = __float2half(s);
}

// ---------------- main GEMM: t-batched, double-buffered B ----------------
// CTA: M=128 rows (rb), N=128, K=128; loops over TC=4 time steps reusing A.
// 8 warps as 4(m) x 2(n), warp tile 32x64.
#define TC 4
#define A_STRIDE 272            // bytes: 128 fp16 + 8 pad
#define SM_A 0
#define SM_B0 (SM_A + 128 * A_STRIDE)         // 34816
#define SM_B1 (SM_B0 + 128 * A_STRIDE)        // 69632
#define SM_TOTAL (SM_B1 + 128 * A_STRIDE)     // 104448

__global__ void __launch_bounds__(256, 2)
gemm_kernel(float* __restrict__ out) {
    extern __shared__ __align__(16) char smem[];
    int tid = threadIdx.x;
    int rb = blockIdx.x, t0 = blockIdx.y * TC;

    const __half* Ah = g_xh + (size_t)rb * 128 * DD;
    uint32_t sb = smem_u32(smem);

    // ---- A tile: plain vectorized loads (resident for all TC steps) ----
#pragma unroll
    for (int j = 0; j < 8; j++) {
        int idx = j * 256 + tid;
        int row = idx >> 4, c = idx & 15;
        *(float4*)(smem + SM_A + row * A_STRIDE + c * 16) =
            *(const float4*)(Ah + row * DD + c * 8);
    }
    // ---- B[t0] via cp.async into buffer 0 ----
    {
        int row = tid >> 1, c = tid & 1;     // 256 threads x 2 chunks... need 8 per thread
#pragma unroll
        for (int j = 0; j < 8; j++) {
            int idx = j * 256 + tid;
            int r = idx >> 4, cc = idx & 15;
            cp16(sb + SM_B0 + r * A_STRIDE + cc * 16, g_Bf[t0] + r * DD + cc * 8);
        }
        (void)row; (void)c;
    }
    asm volatile("cp.async.commit_group;" ::: "memory");

    int wid = tid >> 5, lane = tid & 31;
    int wm = wid & 3, wn = wid >> 2;
    uint32_t offA = (uint32_t)((wm * 32 + (lane & 15)) * A_STRIDE + (lane >> 4) * 16);
    uint32_t offB = (uint32_t)(((lane & 7) + ((lane >> 3) & 1) * 8) * A_STRIDE +
                               (wn * 64 + (lane >> 4) * 8) * 2);
    uint32_t Ab = sb + SM_A + offA;
    uint32_t Bbuf[2] = {sb + SM_B0 + offB, sb + SM_B1 + offB};
    uint32_t Braw[2] = {sb + SM_B0, sb + SM_B1};

    int g = lane >> 2, q = lane & 3;
    size_t rowbase = (size_t)rb * 128 + wm * 32;

#pragma unroll
    for (int tt = 0; tt < TC; tt++) {
        // issue B[t+1] into the other buffer (previous reads of it were fenced
        // by the trailing __syncthreads of iteration tt-1)
        if (tt < TC - 1) {
            const __half* Bn = g_Bf[t0 + tt + 1];
            uint32_t dst = Braw[(tt + 1) & 1];
#pragma unroll
            for (int j = 0; j < 8; j++) {
                int idx = j * 256 + tid;
                int r = idx >> 4, cc = idx & 15;
                cp16(dst + r * A_STRIDE + cc * 16, Bn + r * DD + cc * 8);
            }
            asm volatile("cp.async.commit_group;" ::: "memory");
            asm volatile("cp.async.wait_group 1;" ::: "memory");   // B[tt] done
        } else {
            asm volatile("cp.async.wait_group 0;" ::: "memory");
        }
        __syncthreads();

        uint32_t Bb = Bbuf[tt & 1];
        float acc[2][8][4];
#pragma unroll
        for (int i = 0; i < 2; i++)
#pragma unroll
            for (int j = 0; j < 8; j++)
#pragma unroll
                for (int k = 0; k < 4; k++) acc[i][j][k] = 0.0f;

#pragma unroll
        for (int ks = 0; ks < 8; ks++) {
            uint32_t a0[4], a1[4];
            ldsm4(a0, Ab + ks * 32);
            ldsm4(a1, Ab + ks * 32 + 16 * A_STRIDE);
#pragma unroll
            for (int j = 0; j < 4; j++) {
                uint32_t b[4];
                ldsm4t(b, Bb + ks * 16 * A_STRIDE + j * 32);
                mma16816(acc[0][2 * j],     a0, b[0], b[1]);
                mma16816(acc[0][2 * j + 1], a0, b[2], b[3]);
                mma16816(acc[1][2 * j],     a1, b[0], b[1]);
                mma16816(acc[1][2 * j + 1], a1, b[2], b[3]);
            }
        }

        // epilogue for this t (register-only; overlaps next B's cp.async)
        int t = t0 + tt;
#pragma unroll
        for (int mt = 0; mt < 2; mt++) {
            size_t row = rowbase + mt * 16 + g;
#pragma unroll
            for (int nb = 0; nb < 8; nb++) {
                int col = wn * 64 + nb * 8 + q * 2;
                float* o = out + (row * TT + t) * DD + col;
                *(float2*)o = make_float2(acc[mt][nb][0], acc[mt][nb][1]);
                *(float2*)(o + (size_t)8 * TT * DD) = make_float2(acc[mt][nb][2], acc[mt][nb][3]);
            }
        }
        __syncthreads();   // protect buffer (tt+1)&1 before next overwrite
    }
}

// ---------------- launch ----------------
extern "C" void kernel_launch(void* const* d_in, const int* in_sizes, int n_in,
                              void* d_out, int out_size) {
    const float* x = (const float*)d_in[0];
    const float* W = (const float*)d_in[1];
    float* out = (float*)d_out;

    prep_kernel<<<(BB * DD) / 256, 256>>>(x, W);
    power_round_kernel<<<dim3(16, 1), 256>>>(1);   // A^2
    power_round_kernel<<<dim3(16, 2), 256>>>(2);   // A^3, A^4
    power_round_kernel<<<dim3(16, 4), 256>>>(4);   // A^5..A^8
    combine_kernel<<<dim3((DD * DD) / 256, TT), 256>>>();

    cudaFuncSetAttribute(gemm_kernel, cudaFuncAttributeMaxDynamicSharedMemorySize, SM_TOTAL);
    gemm_kernel<<<dim3(BB / 128, TT / TC), 256, SM_TOTAL>>>(out);
}